// round 2
// baseline (speedup 1.0000x reference)
#include <cuda_runtime.h>

// MinGRU: B=8, T=8192, D=512, H=512.
//   k  = x @ Wz^T + bz ; th = x @ Wh^T + bh        (two GEMMs, M=65536,N=512,K=512)
//   z = sigmoid(k); a = sigmoid(-k) = 1-z; g = th>=0 ? th+0.5 : sigmoid(th)
//   h[t] = a[t]*h[t-1] + z[t]*g[t],  h[-1]=0   (== reference log-space scan, but
//   direct-space is stable since a in (0,1), b > 0)
//
// Pipeline:
//   K1 gemm_dual : both projections fused (shared A tile), epilogue computes
//                  a and b, stores interleaved (a,b) float2 pairs to scratch.
//   K2 phase1    : per-chunk (len 128) aggregates (A=prod a, B=chunk recurrence)
//   K3 phase2    : tiny inter-chunk serial scan per sequence -> carry-in table
//   K4 phase3    : re-scan chunks with carry, write output.

constexpr int B_ = 8;
constexpr int T_ = 8192;
constexpr int D_ = 512;
constexpr int H_ = 512;
constexpr int M_ = B_ * T_;          // 65536
constexpr int CHUNK = 128;
constexpr int NC = T_ / CHUNK;       // 64
constexpr int SEQS = B_ * H_;        // 4096

// Scratch (static device arrays; no runtime allocation allowed)
__device__ float2 g_ab[(size_t)M_ * H_];  // (a,b) per element, 256 MiB
__device__ float g_Aagg[NC * SEQS];
__device__ float g_Bagg[NC * SEQS];
__device__ float g_carry[NC * SEQS];

// ---------------------------------------------------------------------------
// K1: fused dual GEMM + gating epilogue.
// Block: 128(M) x 64(N) tile of BOTH outputs; 256 threads; micro-tile 8x4 each.
// ---------------------------------------------------------------------------
__global__ __launch_bounds__(256) void gemm_dual_kernel(
    const float* __restrict__ x,
    const float* __restrict__ Wz, const float* __restrict__ bz,
    const float* __restrict__ Wh, const float* __restrict__ bh)
{
    constexpr int BM = 128, BN = 64, BK = 16, TM = 8, TN = 4;

    __shared__ float As [BK][BM + 4];
    __shared__ float Bzs[BK][BN + 4];
    __shared__ float Bhs[BK][BN + 4];

    const int m0  = blockIdx.x * BM;
    const int n0  = blockIdx.y * BN;
    const int tid = threadIdx.x;
    const int tm  = tid >> 4;         // 0..15 -> rows tm*8..tm*8+7
    const int tn  = tid & 15;         // 0..15 -> cols tn*4..tn*4+3

    // load mapping: lr = row 0..63, lc = col {0,4,8,12}
    const int lr = tid >> 2;
    const int lc = (tid & 3) << 2;

    float ck[TM][TN], ch[TM][TN];
#pragma unroll
    for (int i = 0; i < TM; i++)
#pragma unroll
        for (int j = 0; j < TN; j++) { ck[i][j] = 0.f; ch[i][j] = 0.f; }

    const float* xA0 = x  + (size_t)(m0 + lr)      * D_ + lc;
    const float* xA1 = x  + (size_t)(m0 + lr + 64) * D_ + lc;
    const float* wzp = Wz + (size_t)(n0 + lr)      * D_ + lc;
    const float* whp = Wh + (size_t)(n0 + lr)      * D_ + lc;

    for (int k0 = 0; k0 < D_; k0 += BK) {
        float4 a0 = *(const float4*)(xA0 + k0);
        float4 a1 = *(const float4*)(xA1 + k0);
        float4 z4 = *(const float4*)(wzp + k0);
        float4 h4 = *(const float4*)(whp + k0);

        __syncthreads();
        As[lc + 0][lr]      = a0.x; As[lc + 1][lr]      = a0.y;
        As[lc + 2][lr]      = a0.z; As[lc + 3][lr]      = a0.w;
        As[lc + 0][lr + 64] = a1.x; As[lc + 1][lr + 64] = a1.y;
        As[lc + 2][lr + 64] = a1.z; As[lc + 3][lr + 64] = a1.w;
        Bzs[lc + 0][lr] = z4.x; Bzs[lc + 1][lr] = z4.y;
        Bzs[lc + 2][lr] = z4.z; Bzs[lc + 3][lr] = z4.w;
        Bhs[lc + 0][lr] = h4.x; Bhs[lc + 1][lr] = h4.y;
        Bhs[lc + 2][lr] = h4.z; Bhs[lc + 3][lr] = h4.w;
        __syncthreads();

#pragma unroll
        for (int kk = 0; kk < BK; kk++) {
            float af[TM], zf[TN], hf[TN];
#pragma unroll
            for (int i = 0; i < TM; i++) af[i] = As[kk][tm * TM + i];
#pragma unroll
            for (int j = 0; j < TN; j++) { zf[j] = Bzs[kk][tn * TN + j];
                                           hf[j] = Bhs[kk][tn * TN + j]; }
#pragma unroll
            for (int i = 0; i < TM; i++)
#pragma unroll
                for (int j = 0; j < TN; j++) {
                    ck[i][j] = fmaf(af[i], zf[j], ck[i][j]);
                    ch[i][j] = fmaf(af[i], hf[j], ch[i][j]);
                }
        }
    }

    // epilogue: gating, write interleaved (a,b) pairs
    float bzr[TN], bhr[TN];
#pragma unroll
    for (int j = 0; j < TN; j++) {
        bzr[j] = bz[n0 + tn * TN + j];
        bhr[j] = bh[n0 + tn * TN + j];
    }

#pragma unroll
    for (int i = 0; i < TM; i++) {
        const int m = m0 + tm * TM + i;
        float2 ab[TN];
#pragma unroll
        for (int j = 0; j < TN; j++) {
            float kv = ck[i][j] + bzr[j];
            float th = ch[i][j] + bhr[j];
            float z  = 1.f / (1.f + __expf(-kv));   // sigmoid(k)
            float a  = 1.f / (1.f + __expf(kv));    // sigmoid(-k) = 1-z (no cancellation)
            float g  = (th >= 0.f) ? (th + 0.5f) : (1.f / (1.f + __expf(-th)));
            ab[j].x = a;
            ab[j].y = z * g;
        }
        float2* po = g_ab + (size_t)m * H_ + n0 + tn * TN;
        // two float4 stores (each = two float2 pairs)
        *(float4*)(po + 0) = make_float4(ab[0].x, ab[0].y, ab[1].x, ab[1].y);
        *(float4*)(po + 2) = make_float4(ab[2].x, ab[2].y, ab[3].x, ab[3].y);
    }
}

// ---------------------------------------------------------------------------
// K2: per-chunk aggregates. grid (H/128, NC, B), 128 threads (one per h).
// ---------------------------------------------------------------------------
__global__ __launch_bounds__(128) void scan_phase1_kernel()
{
    const int h = blockIdx.x * 128 + threadIdx.x;
    const int c = blockIdx.y;
    const int b = blockIdx.z;
    const float2* p = g_ab + ((size_t)b * T_ + (size_t)c * CHUNK) * H_ + h;

    float A = 1.f, hv = 0.f;
#pragma unroll 8
    for (int i = 0; i < CHUNK; i++) {
        float2 ab = p[(size_t)i * H_];
        A *= ab.x;
        hv = fmaf(ab.x, hv, ab.y);
    }
    const int seq = b * H_ + h;
    g_Aagg[c * SEQS + seq] = A;
    g_Bagg[c * SEQS + seq] = hv;
}

// ---------------------------------------------------------------------------
// K3: inter-chunk serial scan. 4096 threads total, coalesced ([c][seq] layout).
// ---------------------------------------------------------------------------
__global__ __launch_bounds__(128) void scan_phase2_kernel()
{
    const int seq = blockIdx.x * blockDim.x + threadIdx.x;
    float hv = 0.f;
#pragma unroll
    for (int c = 0; c < NC; c++) {
        g_carry[c * SEQS + seq] = hv;
        hv = fmaf(g_Aagg[c * SEQS + seq], hv, g_Bagg[c * SEQS + seq]);
    }
}

// ---------------------------------------------------------------------------
// K4: apply carry, write output.
// ---------------------------------------------------------------------------
__global__ __launch_bounds__(128) void scan_phase3_kernel(float* __restrict__ out)
{
    const int h = blockIdx.x * 128 + threadIdx.x;
    const int c = blockIdx.y;
    const int b = blockIdx.z;
    const int seq = b * H_ + h;
    const size_t base = ((size_t)b * T_ + (size_t)c * CHUNK) * H_ + h;
    const float2* p = g_ab + base;
    float* po = out + base;

    float hv = g_carry[c * SEQS + seq];
#pragma unroll 8
    for (int i = 0; i < CHUNK; i++) {
        float2 ab = p[(size_t)i * H_];
        hv = fmaf(ab.x, hv, ab.y);
        po[(size_t)i * H_] = hv;
    }
}

// ---------------------------------------------------------------------------
extern "C" void kernel_launch(void* const* d_in, const int* in_sizes, int n_in,
                              void* d_out, int out_size)
{
    (void)in_sizes; (void)n_in; (void)out_size;
    const float* x  = (const float*)d_in[0];
    const float* Wz = (const float*)d_in[1];
    const float* bz = (const float*)d_in[2];
    const float* Wh = (const float*)d_in[3];
    const float* bh = (const float*)d_in[4];
    float* out = (float*)d_out;

    dim3 gg(M_ / 128, H_ / 64);                 // (512, 8)
    gemm_dual_kernel<<<gg, 256>>>(x, Wz, bz, Wh, bh);

    dim3 g1(H_ / 128, NC, B_);                  // (4, 64, 8)
    scan_phase1_kernel<<<g1, 128>>>();
    scan_phase2_kernel<<<SEQS / 128, 128>>>();
    scan_phase3_kernel<<<g1, 128>>>(out);
}

// round 6
// speedup vs baseline: 1.3268x; 1.3268x over previous
#include <cuda_runtime.h>
#include <cuda_bf16.h>
#include <cstdint>

// MinGRU B=8,T=8192,D=512,H=512 — bf16 split-precision HMMA GEMM + chunked scan.
// (tcgen05 is NOT available: harness builds PTX at compute_100, which rejects
//  tcgen05.*; mma.sync/ldmatrix/cp.async are sm_80-portable and compile fine.)
//
//   k  = x@Wz^T + bz ; th = x@Wh^T + bh
//   a = sigmoid(-k); b = sigmoid(k)*g(th); h[t] = a[t]h[t-1] + b[t]
//
// GEMM: x = xh + xl (bf16), W = wh + wl (bf16); x*W ~= xh*wh + xh*wl + xl*wh
// (drop xl*wl ~ 2^-16 rel). A buf [M][1024] = [hi|lo]; B buf [1024][1024] =
// [hi|lo] rows, N-interleaved: row 2h = Wz[h], row 2h+1 = Wh[h].
// mma.sync m16n8k16 row.col: both operands K-contiguous. C frag gives each
// thread an (even,odd) col pair = (k, th) of one head -> fused gating epilogue.

constexpr int B_ = 8, T_ = 8192, D_ = 512, H_ = 512;
constexpr int M_ = B_ * T_;            // 65536
constexpr int CHUNK = 128, NC = T_ / CHUNK, SEQS = B_ * H_;

constexpr int BM = 128, BN = 128, BK = 32;     // CTA tile
constexpr int NK = 48;                          // 24 stages of 64 cols = 48 BK iters
constexpr int LDS = BK + 8;                     // padded smem row (bf16 units) = 40

// ---- scratch (no runtime allocation allowed) ----
__device__ __align__(16) __nv_bfloat16 g_A[(size_t)M_ * 1024];   // 128 MiB [hi|lo]
__device__ __align__(16) __nv_bfloat16 g_Bm[1024 * 1024];        // 2 MiB  [hi|lo]
__device__ __align__(16) float2 g_ab[(size_t)M_ * H_];           // 256 MiB (a,b)
__device__ float g_Aagg[NC * SEQS];
__device__ float g_Bagg[NC * SEQS];
__device__ float g_carry[NC * SEQS];

// ---- helpers ----
__device__ __forceinline__ uint32_t smem_u32(const void* p) {
    uint32_t a;
    asm("{ .reg .u64 t; cvta.to.shared.u64 t, %1; cvt.u32.u64 %0, t; }" : "=r"(a) : "l"(p));
    return a;
}
__device__ __forceinline__ void cp_async16(uint32_t saddr, const void* gaddr) {
    asm volatile("cp.async.cg.shared.global [%0], [%1], 16;\n" :: "r"(saddr), "l"(gaddr));
}
#define CP_COMMIT() asm volatile("cp.async.commit_group;\n" ::: "memory")
#define CP_WAIT1()  asm volatile("cp.async.wait_group 1;\n" ::: "memory")

__device__ __forceinline__ void ldsm_x4(uint32_t& r0, uint32_t& r1, uint32_t& r2,
                                        uint32_t& r3, uint32_t addr) {
    asm volatile("ldmatrix.sync.aligned.m8n8.x4.shared.b16 {%0,%1,%2,%3}, [%4];"
                 : "=r"(r0), "=r"(r1), "=r"(r2), "=r"(r3) : "r"(addr));
}
__device__ __forceinline__ void mma16816(float* c, const uint32_t* a, const uint32_t* b) {
    asm volatile(
        "mma.sync.aligned.m16n8k16.row.col.f32.bf16.bf16.f32 "
        "{%0,%1,%2,%3}, {%4,%5,%6,%7}, {%8,%9}, {%0,%1,%2,%3};"
        : "+f"(c[0]), "+f"(c[1]), "+f"(c[2]), "+f"(c[3])
        : "r"(a[0]), "r"(a[1]), "r"(a[2]), "r"(a[3]), "r"(b[0]), "r"(b[1]));
}

// ---------------------------------------------------------------------------
// prep: split fp32 -> (hi, lo) bf16 pairs
// ---------------------------------------------------------------------------
__global__ __launch_bounds__(256) void prep_x_kernel(const float* __restrict__ x)
{
    const size_t idx = (size_t)blockIdx.x * 256 + threadIdx.x;   // over M_*D_/4
    const int m = (int)(idx >> 7);          // D_/4 = 128
    const int kq = (int)(idx & 127);
    float4 v = *(const float4*)(x + (size_t)m * D_ + kq * 4);
    __nv_bfloat16 h[4], l[4];
    const float* vp = (const float*)&v;
#pragma unroll
    for (int i = 0; i < 4; i++) {
        h[i] = __float2bfloat16_rn(vp[i]);
        l[i] = __float2bfloat16_rn(vp[i] - __bfloat162float(h[i]));
    }
    *(uint2*)(g_A + (size_t)m * 1024 + kq * 4)       = *(uint2*)h;
    *(uint2*)(g_A + (size_t)m * 1024 + 512 + kq * 4) = *(uint2*)l;
}

__global__ __launch_bounds__(256) void prep_w_kernel(
    const float* __restrict__ Wz, const float* __restrict__ Wh)
{
    const int idx = blockIdx.x * 256 + threadIdx.x;   // over 1024*512/4
    const int n = idx >> 7;
    const int kq = idx & 127;
    const int hrow = n >> 1;
    const float* W = (n & 1) ? Wh : Wz;
    float4 v = *(const float4*)(W + (size_t)hrow * D_ + kq * 4);
    __nv_bfloat16 h[4], l[4];
    const float* vp = (const float*)&v;
#pragma unroll
    for (int i = 0; i < 4; i++) {
        h[i] = __float2bfloat16_rn(vp[i]);
        l[i] = __float2bfloat16_rn(vp[i] - __bfloat162float(h[i]));
    }
    *(uint2*)(g_Bm + (size_t)n * 1024 + kq * 4)       = *(uint2*)h;
    *(uint2*)(g_Bm + (size_t)n * 1024 + 512 + kq * 4) = *(uint2*)l;
}

// ---------------------------------------------------------------------------
// GEMM: 128x128 CTA tile, 8 warps (2 M x 4 N) of 64x32, double-buffered.
// grid (8, 512): x = N-tile (adjacent CTAs share A tile in L2), y = M-tile.
// ---------------------------------------------------------------------------
__global__ __launch_bounds__(256, 1) void gemm_mma_kernel(
    const float* __restrict__ bz, const float* __restrict__ bh)
{
    __shared__ __align__(16) __nv_bfloat16 As[2][BM][LDS];
    __shared__ __align__(16) __nv_bfloat16 Bs[2][BN][LDS];

    const int tid  = threadIdx.x;
    const int lane = tid & 31;
    const int wid  = tid >> 5;
    const int wm   = wid & 1;          // 0..1 : M offset wm*64
    const int wn   = wid >> 1;         // 0..3 : N offset wn*32
    const int m0   = blockIdx.y * BM;
    const int n0   = blockIdx.x * BN;

    const uint32_t sA = smem_u32(&As[0][0][0]);
    const uint32_t sB = smem_u32(&Bs[0][0][0]);
    constexpr uint32_t ASTG = BM * LDS * 2;      // bytes per A stage
    constexpr uint32_t BSTG = BN * LDS * 2;

    // cp.async mapping: 512 chunks of 16B per tile; thread -> 2 chunks.
    const int lr = tid >> 2;            // row 0..63 (two passes below)
    const int lc = (tid & 3) * 8;       // col offset in bf16 (8 bf16 = 16B)

    auto load_stage = [&](int buf, int it) {
        const int st = it >> 1;                          // 0..23
        const int ka = (st < 8) ? st : st - 8;           // A 64-col block
        const int kb = (st < 16) ? st : st - 16;         // B 64-col block
        const int kA = ka * 64 + (it & 1) * 32;          // col in [0,1024)
        const int kB = kb * 64 + (it & 1) * 32;
        const __nv_bfloat16* Ag = g_A  + (size_t)(m0) * 1024 + kA;
        const __nv_bfloat16* Bg = g_Bm + (size_t)(n0) * 1024 + kB;
        uint32_t as = sA + buf * ASTG;
        uint32_t bs = sB + buf * BSTG;
#pragma unroll
        for (int i = 0; i < 2; i++) {
            int r = lr + i * 64;
            cp_async16(as + (r * LDS + lc) * 2, Ag + (size_t)r * 1024 + lc);
            cp_async16(bs + (r * LDS + lc) * 2, Bg + (size_t)r * 1024 + lc);
        }
    };

    float c[4][4][4];
#pragma unroll
    for (int i = 0; i < 4; i++)
#pragma unroll
        for (int j = 0; j < 4; j++)
#pragma unroll
            for (int q = 0; q < 4; q++) c[i][j][q] = 0.f;

    // ldmatrix address components (within a stage)
    const int a_r  = lane & 15;                 // row 0..15
    const int a_kc = (lane >> 4) * 8;           // k sub-offset 0/8
    const int b_nr = (lane & 7) + ((lane >> 4) << 3);   // n row 0..15
    const int b_kc = ((lane >> 3) & 1) * 8;

    load_stage(0, 0);
    CP_COMMIT();

    for (int it = 0; it < NK; it++) {
        if (it + 1 < NK) load_stage((it + 1) & 1, it + 1);
        CP_COMMIT();
        CP_WAIT1();
        __syncthreads();

        const int buf = it & 1;
        const uint32_t aw = sA + buf * ASTG +
                            ((wm * 64 + a_r) * LDS + a_kc) * 2;
        const uint32_t bw = sB + buf * BSTG +
                            ((wn * 32 + b_nr) * LDS + b_kc) * 2;

        uint32_t af[2][4][4];   // [k16][mi][4]
        uint32_t bf[2][4][2];   // [k16][ni][2]
#pragma unroll
        for (int k16 = 0; k16 < 2; k16++) {
#pragma unroll
            for (int mi = 0; mi < 4; mi++)
                ldsm_x4(af[k16][mi][0], af[k16][mi][1], af[k16][mi][2], af[k16][mi][3],
                        aw + (mi * 16 * LDS + k16 * 16) * 2);
#pragma unroll
            for (int nn = 0; nn < 2; nn++) {
                uint32_t r0, r1, r2, r3;
                ldsm_x4(r0, r1, r2, r3, bw + (nn * 16 * LDS + k16 * 16) * 2);
                bf[k16][2 * nn][0]     = r0; bf[k16][2 * nn][1]     = r1;
                bf[k16][2 * nn + 1][0] = r2; bf[k16][2 * nn + 1][1] = r3;
            }
        }
#pragma unroll
        for (int k16 = 0; k16 < 2; k16++)
#pragma unroll
            for (int mi = 0; mi < 4; mi++)
#pragma unroll
                for (int ni = 0; ni < 4; ni++)
                    mma16816(c[mi][ni], af[k16][mi], bf[k16][ni]);
        __syncthreads();
    }

    // epilogue: per thread, C cols (2q, 2q+1) = (k, th) of head h.
    const int gq = lane >> 2;       // row within m16
    const int tq = lane & 3;
    float bzv[4], bhv[4];
#pragma unroll
    for (int ni = 0; ni < 4; ni++) {
        const int h = ((n0 + wn * 32 + ni * 8) >> 1) + tq;
        bzv[ni] = __ldg(bz + h);
        bhv[ni] = __ldg(bh + h);
    }
#pragma unroll
    for (int mi = 0; mi < 4; mi++) {
#pragma unroll
        for (int ni = 0; ni < 4; ni++) {
            const int h = ((n0 + wn * 32 + ni * 8) >> 1) + tq;
#pragma unroll
            for (int half = 0; half < 2; half++) {
                const int m = m0 + wm * 64 + mi * 16 + gq + half * 8;
                float kv = c[mi][ni][2 * half]     + bzv[ni];
                float th = c[mi][ni][2 * half + 1] + bhv[ni];
                float z  = 1.f / (1.f + __expf(-kv));
                float a  = 1.f / (1.f + __expf(kv));
                float g  = (th >= 0.f) ? (th + 0.5f) : (1.f / (1.f + __expf(-th)));
                g_ab[(size_t)m * H_ + h] = make_float2(a, z * g);
            }
        }
    }
}

// ---------------------------------------------------------------------------
// scan kernels (unchanged, known-good)
// ---------------------------------------------------------------------------
__global__ __launch_bounds__(128) void scan_phase1_kernel()
{
    const int h = blockIdx.x * 128 + threadIdx.x;
    const int c = blockIdx.y;
    const int b = blockIdx.z;
    const float2* p = g_ab + ((size_t)b * T_ + (size_t)c * CHUNK) * H_ + h;
    float A = 1.f, hv = 0.f;
#pragma unroll 8
    for (int i = 0; i < CHUNK; i++) {
        float2 ab = p[(size_t)i * H_];
        A *= ab.x;
        hv = fmaf(ab.x, hv, ab.y);
    }
    const int seq = b * H_ + h;
    g_Aagg[c * SEQS + seq] = A;
    g_Bagg[c * SEQS + seq] = hv;
}

__global__ __launch_bounds__(128) void scan_phase2_kernel()
{
    const int seq = blockIdx.x * blockDim.x + threadIdx.x;
    float hv = 0.f;
#pragma unroll
    for (int c = 0; c < NC; c++) {
        g_carry[c * SEQS + seq] = hv;
        hv = fmaf(g_Aagg[c * SEQS + seq], hv, g_Bagg[c * SEQS + seq]);
    }
}

__global__ __launch_bounds__(128) void scan_phase3_kernel(float* __restrict__ out)
{
    const int h = blockIdx.x * 128 + threadIdx.x;
    const int c = blockIdx.y;
    const int b = blockIdx.z;
    const int seq = b * H_ + h;
    const size_t base = ((size_t)b * T_ + (size_t)c * CHUNK) * H_ + h;
    const float2* p = g_ab + base;
    float* po = out + base;
    float hv = g_carry[c * SEQS + seq];
#pragma unroll 8
    for (int i = 0; i < CHUNK; i++) {
        float2 ab = p[(size_t)i * H_];
        hv = fmaf(ab.x, hv, ab.y);
        po[(size_t)i * H_] = hv;
    }
}

// ---------------------------------------------------------------------------
extern "C" void kernel_launch(void* const* d_in, const int* in_sizes, int n_in,
                              void* d_out, int out_size)
{
    (void)in_sizes; (void)n_in; (void)out_size;
    const float* x  = (const float*)d_in[0];
    const float* Wz = (const float*)d_in[1];
    const float* bz = (const float*)d_in[2];
    const float* Wh = (const float*)d_in[3];
    const float* bh = (const float*)d_in[4];
    float* out = (float*)d_out;

    prep_x_kernel<<<(int)((size_t)M_ * D_ / 4 / 256), 256>>>(x);
    prep_w_kernel<<<1024 * 512 / 4 / 256, 256>>>(Wz, Wh);

    dim3 gg(1024 / BN, M_ / BM);       // (8, 512)
    gemm_mma_kernel<<<gg, 256>>>(bz, bh);

    dim3 g1(H_ / 128, NC, B_);
    scan_phase1_kernel<<<g1, 128>>>();
    scan_phase2_kernel<<<SEQS / 128, 128>>>();
    scan_phase3_kernel<<<g1, 128>>>(out);
}